// round 4
// baseline (speedup 1.0000x reference)
#include <cuda_runtime.h>
#include <cstdint>

#define BB   8
#define CC   64
#define NP   12800
#define NS   3200
#define KNN  16
#define HWD  19200
#define NOUT 22400   // HWD + NS

// ---------------- scratch (device globals; no allocation) ----------------
__device__ __align__(16) float g_pT   [(size_t)BB * NP * CC];   // p_feat transposed   [B, NP, 64]
__device__ __align__(16) float g_rgbT [(size_t)BB * HWD * CC];  // rgb transposed      [B, HW, 64]
__device__ __align__(16) float g_pembT[(size_t)BB * NS * CC];   // p_emb0 point-major  [B, NS, 64]
__device__ __align__(16) float g_r2pgT[(size_t)BB * NS * CC];   // rgb gather+max      [B, NS, 64]
__device__ __align__(16) float g_qT   [(size_t)BB * NS * CC];   // Wfuse_p @ p2r       [B, NS, 64]
__device__ __align__(16) float g_r2ppT[(size_t)BB * NS * CC];   // r2p_pre             [B, NS, 64]

// ---------------- transpose [B,64,N] -> [B,N,64] ----------------
__device__ __forceinline__ void transpose_body(const float* __restrict__ src,
                                               float* __restrict__ dst, int N) {
    __shared__ __align__(16) float s[32][33];
    const int b  = blockIdx.z;
    const int n0 = blockIdx.x * 32;
    const int c0 = blockIdx.y * 32;
    const int tx = threadIdx.x, ty = threadIdx.y;
    const float* sp = src + ((size_t)b * CC + c0) * N + n0;
#pragma unroll
    for (int i = 0; i < 4; i++)
        s[ty + 8 * i][tx] = sp[(size_t)(ty + 8 * i) * N + tx];
    __syncthreads();
    float* dp = dst + ((size_t)b * N + n0) * CC + c0;
#pragma unroll
    for (int i = 0; i < 4; i++)
        dp[(size_t)(ty + 8 * i) * CC + tx] = s[tx][ty + 8 * i];
}

__global__ void __launch_bounds__(256, 2)
k_transpose_p(const float* __restrict__ src)   { transpose_body(src, g_pT,   NP);  }
__global__ void __launch_bounds__(256, 2)
k_transpose_rgb(const float* __restrict__ src) { transpose_body(src, g_rgbT, HWD); }

// ---------------- gather + maxpool: one warp per (b,m) ----------------
__device__ __forceinline__ void gather_body(const float* __restrict__ srcT,
                                            const int* __restrict__ idx,
                                            float* __restrict__ dstT, int Nsrc) {
    const int wid  = threadIdx.x >> 5;
    const int lane = threadIdx.x & 31;
    const int gid  = blockIdx.x * 8 + wid;      // == b*NS + m
    const int b    = gid / NS;
    const int* ip = idx + (size_t)gid * KNN;
    int id[KNN];
#pragma unroll
    for (int k = 0; k < KNN; k++) id[k] = __ldg(ip + k);
    float2 v[KNN];
#pragma unroll
    for (int k = 0; k < KNN; k++) {
        const float2* r = (const float2*)(srcT + ((size_t)b * Nsrc + id[k]) * CC);
        v[k] = __ldg(r + lane);
    }
    float2 acc = v[0];
#pragma unroll
    for (int k = 1; k < KNN; k++) {
        acc.x = fmaxf(acc.x, v[k].x);
        acc.y = fmaxf(acc.y, v[k].y);
    }
    ((float2*)(dstT + (size_t)gid * CC))[lane] = acc;
}

__global__ void __launch_bounds__(256, 2)
k_gather_p(const int* __restrict__ idx)   { gather_body(g_pT,   idx, g_pembT, NP);  }
__global__ void __launch_bounds__(256, 2)
k_gather_rgb(const int* __restrict__ idx) { gather_body(g_rgbT, idx, g_r2pgT, HWD); }

// ---------------- shared GEMM helpers (64x64 tile, K=64 panel) ----------------
// Xs[c][n], Ws[c][o], rows padded to 68 floats (16B-aligned, conflict-free lds.128)

__device__ __forceinline__ void load_xtile(const float* __restrict__ x,
                                           float (*Xs)[68], int t) {
#pragma unroll
    for (int i = 0; i < 16; i++) {
        int f = t + 256 * i;
        Xs[f & 63][f >> 6] = x[f];     // x is a contiguous 64x64 block [n][c]
    }
}

__device__ __forceinline__ void load_wtile(const float* __restrict__ w, int stride,
                                           float (*Ws)[68], int t) {
#pragma unroll
    for (int i = 0; i < 16; i++) {
        int f = t + 256 * i;
        int o = f >> 6, c = f & 63;
        Ws[c][o] = __ldg(w + (size_t)o * stride + c);
    }
}

__device__ __forceinline__ void gemm_acc(const float (*Ws)[68], const float (*Xs)[68],
                                         int tx, int ty, float acc[4][4]) {
#pragma unroll 8
    for (int c = 0; c < 64; c++) {
        float4 a  = *(const float4*)&Ws[c][4 * ty];
        float4 bb = *(const float4*)&Xs[c][4 * tx];
        acc[0][0] += a.x * bb.x; acc[0][1] += a.x * bb.y; acc[0][2] += a.x * bb.z; acc[0][3] += a.x * bb.w;
        acc[1][0] += a.y * bb.x; acc[1][1] += a.y * bb.y; acc[1][2] += a.y * bb.z; acc[1][3] += a.y * bb.w;
        acc[2][0] += a.z * bb.x; acc[2][1] += a.z * bb.y; acc[2][2] += a.z * bb.z; acc[2][3] += a.z * bb.w;
        acc[3][0] += a.w * bb.x; acc[3][1] += a.w * bb.y; acc[3][2] += a.w * bb.z; acc[3][3] += a.w * bb.w;
    }
}

// ---------------- p2r: t = relu(s*(Wpre@p_emb0)+b); q = Wfuse[:,64:] @ t ----------------
__global__ void __launch_bounds__(256, 1)
k_p2r_preq(const float* __restrict__ w_pre,
           const float* __restrict__ s_pre,
           const float* __restrict__ b_pre,
           const float* __restrict__ w_fuse) {
    __shared__ __align__(16) float Ws[64][68];
    __shared__ __align__(16) float Xs[64][68];
    const int b = blockIdx.y, n0 = blockIdx.x * 64;
    const int tx = threadIdx.x, ty = threadIdx.y;
    const int t = ty * 16 + tx;

    load_xtile(g_pembT + ((size_t)b * NS + n0) * CC, Xs, t);
    load_wtile(w_pre, 64, Ws, t);
    __syncthreads();

    float acc[4][4] = {};
    gemm_acc(Ws, Xs, tx, ty, acc);

    float s4[4], b4[4];
#pragma unroll
    for (int i = 0; i < 4; i++) { s4[i] = __ldg(s_pre + 4 * ty + i); b4[i] = __ldg(b_pre + 4 * ty + i); }

    __syncthreads();   // everyone done reading Xs/Ws
#pragma unroll
    for (int i = 0; i < 4; i++)
#pragma unroll
        for (int j = 0; j < 4; j++)
            Xs[4 * ty + i][4 * tx + j] = fmaxf(acc[i][j] * s4[i] + b4[i], 0.0f);
    load_wtile(w_fuse + 64, 128, Ws, t);   // w_fuse[o][64+c]
    __syncthreads();

    float acc2[4][4] = {};
    gemm_acc(Ws, Xs, tx, ty, acc2);

    float* qp = g_qT + ((size_t)b * NS + n0) * CC;
#pragma unroll
    for (int j = 0; j < 4; j++) {
        int n = 4 * tx + j;
        float4 v = make_float4(acc2[0][j], acc2[1][j], acc2[2][j], acc2[3][j]);
        *(float4*)(qp + (size_t)n * CC + 4 * ty) = v;
    }
}

// ---------------- r2p_pre = relu(s*(W@r2p_gather)+b), point-major out ----------------
__global__ void __launch_bounds__(256, 1)
k_r2p_pre(const float* __restrict__ w,
          const float* __restrict__ s,
          const float* __restrict__ bias) {
    __shared__ __align__(16) float Ws[64][68];
    __shared__ __align__(16) float Xs[64][68];
    const int b = blockIdx.y, n0 = blockIdx.x * 64;
    const int tx = threadIdx.x, ty = threadIdx.y;
    const int t = ty * 16 + tx;

    load_xtile(g_r2pgT + ((size_t)b * NS + n0) * CC, Xs, t);
    load_wtile(w, 64, Ws, t);
    __syncthreads();

    float acc[4][4] = {};
    gemm_acc(Ws, Xs, tx, ty, acc);

    float s4[4], b4[4];
#pragma unroll
    for (int i = 0; i < 4; i++) { s4[i] = __ldg(s + 4 * ty + i); b4[i] = __ldg(bias + 4 * ty + i); }

    float* op = g_r2ppT + ((size_t)b * NS + n0) * CC;
#pragma unroll
    for (int j = 0; j < 4; j++) {
        int n = 4 * tx + j;
        float4 v = make_float4(fmaxf(acc[0][j] * s4[0] + b4[0], 0.0f),
                               fmaxf(acc[1][j] * s4[1] + b4[1], 0.0f),
                               fmaxf(acc[2][j] * s4[2] + b4[2], 0.0f),
                               fmaxf(acc[3][j] * s4[3] + b4[3], 0.0f));
        *(float4*)(op + (size_t)n * CC + 4 * ty) = v;
    }
}

// ---------------- rgb_out = relu(s*(Wr@rgb + q[:, p2r_idx]) + b) ----------------
__global__ void __launch_bounds__(256, 1)
k_rgb_out(const float* __restrict__ w_fuse,
          const float* __restrict__ s,
          const float* __restrict__ bias,
          const int* __restrict__ p2r_idx,
          float* __restrict__ out) {
    __shared__ __align__(16) float Ws[64][68];
    __shared__ __align__(16) float Xs[64][68];
    const int b = blockIdx.y, n0 = blockIdx.x * 64;
    const int tx = threadIdx.x, ty = threadIdx.y;
    const int t = ty * 16 + tx;

    load_xtile(g_rgbT + ((size_t)b * HWD + n0) * CC, Xs, t);
    load_wtile(w_fuse, 128, Ws, t);   // first 64 input channels (rgb half)
    __syncthreads();

    float acc[4][4] = {};
    gemm_acc(Ws, Xs, tx, ty, acc);

    // gathered add of q (interp of point branch commuted through the matmul)
    const int* ip = p2r_idx + (size_t)b * HWD + n0;
#pragma unroll
    for (int j = 0; j < 4; j++) {
        int idx = __ldg(ip + 4 * tx + j);
        float4 q = *(const float4*)(g_qT + ((size_t)b * NS + idx) * CC + 4 * ty);
        acc[0][j] += q.x; acc[1][j] += q.y; acc[2][j] += q.z; acc[3][j] += q.w;
    }

    float s4[4], b4[4];
#pragma unroll
    for (int i = 0; i < 4; i++) { s4[i] = __ldg(s + 4 * ty + i); b4[i] = __ldg(bias + 4 * ty + i); }

#pragma unroll
    for (int i = 0; i < 4; i++) {
        int o = 4 * ty + i;
        float4 v = make_float4(fmaxf(acc[i][0] * s4[i] + b4[i], 0.0f),
                               fmaxf(acc[i][1] * s4[i] + b4[i], 0.0f),
                               fmaxf(acc[i][2] * s4[i] + b4[i], 0.0f),
                               fmaxf(acc[i][3] * s4[i] + b4[i], 0.0f));
        *(float4*)(out + ((size_t)(b * CC + o)) * NOUT + n0 + 4 * tx) = v;
    }
}

// ---------------- p_out = relu(s*(Wf1@p_emb0 + Wf2@r2p_pre) + b) ----------------
__global__ void __launch_bounds__(256, 1)
k_p_out(const float* __restrict__ w_fuse,
        const float* __restrict__ s,
        const float* __restrict__ bias,
        float* __restrict__ out) {
    __shared__ __align__(16) float Ws[64][68];
    __shared__ __align__(16) float Xs[64][68];
    const int b = blockIdx.y, n0 = blockIdx.x * 64;
    const int tx = threadIdx.x, ty = threadIdx.y;
    const int t = ty * 16 + tx;

    float acc[4][4] = {};

    load_xtile(g_pembT + ((size_t)b * NS + n0) * CC, Xs, t);
    load_wtile(w_fuse, 128, Ws, t);
    __syncthreads();
    gemm_acc(Ws, Xs, tx, ty, acc);
    __syncthreads();

    load_xtile(g_r2ppT + ((size_t)b * NS + n0) * CC, Xs, t);
    load_wtile(w_fuse + 64, 128, Ws, t);
    __syncthreads();
    gemm_acc(Ws, Xs, tx, ty, acc);

    float s4[4], b4[4];
#pragma unroll
    for (int i = 0; i < 4; i++) { s4[i] = __ldg(s + 4 * ty + i); b4[i] = __ldg(bias + 4 * ty + i); }

#pragma unroll
    for (int i = 0; i < 4; i++) {
        int o = 4 * ty + i;
        float4 v = make_float4(fmaxf(acc[i][0] * s4[i] + b4[i], 0.0f),
                               fmaxf(acc[i][1] * s4[i] + b4[i], 0.0f),
                               fmaxf(acc[i][2] * s4[i] + b4[i], 0.0f),
                               fmaxf(acc[i][3] * s4[i] + b4[i], 0.0f));
        *(float4*)(out + ((size_t)(b * CC + o)) * NOUT + HWD + n0 + 4 * tx) = v;
    }
}

// ---------------- launch ----------------
extern "C" void kernel_launch(void* const* d_in, const int* in_sizes, int n_in,
                              void* d_out, int out_size) {
    const float* rgb_feat   = (const float*)d_in[0];
    const float* p_feat     = (const float*)d_in[1];
    const float* w_p2r_pre  = (const float*)d_in[2];
    const float* s_p2r_pre  = (const float*)d_in[3];
    const float* b_p2r_pre  = (const float*)d_in[4];
    const float* w_p2r_fuse = (const float*)d_in[5];
    const float* s_p2r_fuse = (const float*)d_in[6];
    const float* b_p2r_fuse = (const float*)d_in[7];
    const float* w_r2p_pre  = (const float*)d_in[8];
    const float* s_r2p_pre  = (const float*)d_in[9];
    const float* b_r2p_pre  = (const float*)d_in[10];
    const float* w_r2p_fuse = (const float*)d_in[11];
    const float* s_r2p_fuse = (const float*)d_in[12];
    const float* b_r2p_fuse = (const float*)d_in[13];
    const int*   pool_idx   = (const int*)d_in[14];
    const int*   p2r_idx    = (const int*)d_in[15];
    const int*   r2p_idx    = (const int*)d_in[16];
    float* out = (float*)d_out;

    dim3 tb(32, 8);
    k_transpose_p  <<<dim3(NP  / 32, 2, BB), tb>>>(p_feat);
    k_transpose_rgb<<<dim3(HWD / 32, 2, BB), tb>>>(rgb_feat);

    k_gather_p  <<<BB * NS / 8, 256>>>(pool_idx);
    k_gather_rgb<<<BB * NS / 8, 256>>>(r2p_idx);

    dim3 gb(16, 16);
    k_p2r_preq<<<dim3(NS / 64, BB), gb>>>(w_p2r_pre, s_p2r_pre, b_p2r_pre, w_p2r_fuse);
    k_r2p_pre <<<dim3(NS / 64, BB), gb>>>(w_r2p_pre, s_r2p_pre, b_r2p_pre);

    k_rgb_out<<<dim3(HWD / 64, BB), gb>>>(w_p2r_fuse, s_p2r_fuse, b_p2r_fuse, p2r_idx, out);
    k_p_out  <<<dim3(NS  / 64, BB), gb>>>(w_r2p_fuse, s_r2p_fuse, b_r2p_fuse, out);
}